// round 13
// baseline (speedup 1.0000x reference)
#include <cuda_runtime.h>
#include <cstdint>

// Problem constants (fixed by setup_inputs)
#define BB 8
#define NN 8192
#define NPOINT 1024
#define NSAMPLE 32
#define DD 64
#define R2 0.0625f
#define OUTCH 67  // 3 + 64

#define FPS_T 512               // threads per block (uniform)
#define CL 8                    // cluster size = FPS CTAs per batch
#define NFPS (BB * CL)          // 64 FPS blocks
#define PTS_CTA (NN / CL)       // 1024 points per FPS CTA (2 per thread)
#define NPREP 128               // prep blocks (512 pts each)
#define BALLW 16                // warps (= centroids) per ball block
#define NBALL (BB * NPOINT / BALLW)   // 512 ball blocks
#define DYN_SMEM 196608         // 192KB for every block -> 1 block/SM
#define PUB 16                  // FPS progress publish granularity

using u64 = unsigned long long;
using u32 = unsigned int;

// ---- packed f32x2 helpers (per-lane IEEE RN, bit-identical to scalar RN ops)
__device__ __forceinline__ u64 pk2(float lo, float hi) {
    u64 r; asm("mov.b64 %0, {%1,%2};" : "=l"(r) : "f"(lo), "f"(hi)); return r;
}
__device__ __forceinline__ void up2(u64 v, float& lo, float& hi) {
    asm("mov.b64 {%0,%1}, %2;" : "=f"(lo), "=f"(hi) : "l"(v));
}
__device__ __forceinline__ u64 add2(u64 a, u64 b) {
    u64 r; asm("add.rn.f32x2 %0, %1, %2;" : "=l"(r) : "l"(a), "l"(b)); return r;
}
__device__ __forceinline__ u64 mul2(u64 a, u64 b) {
    u64 r; asm("mul.rn.f32x2 %0, %1, %2;" : "=l"(r) : "l"(a), "l"(b)); return r;
}
__device__ __forceinline__ u32 smem_u32(const void* p) {
    u32 a;
    asm("{ .reg .u64 t; cvta.to.shared.u64 t, %1; cvt.u32.u64 %0, t; }"
        : "=r"(a) : "l"(p));
    return a;
}
__device__ __forceinline__ u32 mapa_u32(u32 a, u32 rank) {
    u32 o; asm("mapa.shared::cluster.u32 %0, %1, %2;" : "=r"(o) : "r"(a), "r"(rank));
    return o;
}
__device__ __forceinline__ void vsts64(u32 a, u64 v) {
    asm volatile("st.volatile.shared.b64 [%0], %1;" :: "r"(a), "l"(v) : "memory");
}
__device__ __forceinline__ void st_cluster64(u32 a, u64 v) {
    asm volatile("st.shared::cluster.b64 [%0], %1;" :: "r"(a), "l"(v) : "memory");
}

// ---------------------------------------------------------------------------
// Device scratch + producer/consumer counters (zeroed per launch by init)
// ---------------------------------------------------------------------------
__device__ float4 g_pk[BB * NN];   // packed {x,y,z,|p|^2}
__device__ int    g_progress[BB];  // FPS steps published per batch
__device__ int    g_prep_done;     // prep blocks completed

__global__ void init_kernel() {
    if (threadIdx.x < BB) g_progress[threadIdx.x] = 0;
    if (threadIdx.x == BB) g_prep_done = 0;
}

// ---------------------------------------------------------------------------
// Mega kernel, cluster size 8. Blocks 0..63: FPS (8-CTA cluster per batch).
// Blocks 64..191: prep. Blocks 192..703: ball. FPS clusters are exactly
// blocks 8c..8c+7 (c<8), so prep/ball clusters never execute cluster ops.
//
// FPS: BARRIER-FREE warp-key all-to-all (R12 scheme, scaled to 8 CTAs).
//  - 128 warps per batch (16/CTA x 8 CTAs); warp (r,w) owns slot r*16+w on
//    every CTA; double-buffered by it&1 (128 slots = 1KB per buffer).
//  - per step each warp: packed exact dist update over its 2 points
//    (bit-identical to jnp), argmax ('>=' keeps left => smallest index on
//    ties), warp REDUX pair -> key = (val<<32)|((8191-idx)<<2)|(it&3).
//    REDUX results are warp-uniform, so lanes 0..7 EACH post the key to one
//    CTA of the cluster (parallel posting, no lane0 serialization). Single
//    aligned 8B store = atomic; key IS the payload -> no fence needed.
//  - each warp polls all 128 slots (4/lane via 2x ld.volatile.v2.u64) until
//    every tag == it&3, 4-way pair-max, then hi/lo REDUX -> global winner.
//    max key = max value, ties -> max(8191-idx) = smallest index =
//    jnp.argmax first-occurrence (tag bits equal across a step).
//  - slot-reuse safety: unchanged from R12 (buffer b's consecutive users are
//    steps it, it+2 with different tags; a writer reaches it+2 only after
//    polling it+1, which requires every warp to have finished polling it).
//    Slots init to tag=2; one startup cluster.sync. NO per-step barrier or
//    fence of any scope.
// ---------------------------------------------------------------------------
__global__ void __launch_bounds__(FPS_T, 1) __cluster_dims__(CL, 1, 1)
mega_kernel(const float* __restrict__ xyz, const float* __restrict__ points,
            float* __restrict__ new_xyz, float* __restrict__ new_points) {
    extern __shared__ u64 dynsmem[];
    const int bid = blockIdx.x;
    const int tid = threadIdx.x;
    const int lane = tid & 31;
    const int w    = tid >> 5;

    // =========================== PREP path ================================
    if (bid >= NFPS && bid < NFPS + NPREP) {
        int i = (bid - NFPS) * FPS_T + tid;      // 0 .. BB*NN-1
        const float* p = xyz + (size_t)i * 3;
        float x = __ldg(p + 0), y = __ldg(p + 1), z = __ldg(p + 2);
        float dn = __fadd_rn(__fadd_rn(__fmul_rn(x, x), __fmul_rn(y, y)),
                             __fmul_rn(z, z));
        g_pk[i] = make_float4(x, y, z, dn);
        __syncthreads();
        if (tid == 0) {
            int dummy;
            asm volatile("atom.add.release.gpu.global.s32 %0, [%1], 1;"
                         : "=r"(dummy) : "l"(&g_prep_done) : "memory");
        }
        return;
    }

    // ============================ FPS path =================================
    if (bid < NFPS) {
        u64* sneg = dynsmem;                      // [NN*3] negated dup table
        __shared__ u64 slots[2][128];             // [buf][cta*16+warp]

        const int b       = bid >> 3;
        const u32 rank    = (u32)(bid & 7);
        const int pbase   = (int)rank * PTS_CTA;
        const float* xb   = xyz + (size_t)b * NN * 3;

        // full-batch negated table (every CTA keeps its own copy)
        for (int j = tid; j < NN; j += FPS_T) {
            float x = __ldg(xb + j * 3 + 0);
            float y = __ldg(xb + j * 3 + 1);
            float z = __ldg(xb + j * 3 + 2);
            sneg[3 * j + 0] = pk2(-x, -x);
            sneg[3 * j + 1] = pk2(-y, -y);
            sneg[3 * j + 2] = pk2(-z, -z);
        }
        // own 2 points (k = 0..1 at pbase + tid + k*512), one packed pair
        u64 px2, py2, pz2;
        u32 du[2];
        {
            int j0 = pbase + tid, j1 = pbase + tid + FPS_T;
            px2 = pk2(__ldg(xb + j0 * 3 + 0), __ldg(xb + j1 * 3 + 0));
            py2 = pk2(__ldg(xb + j0 * 3 + 1), __ldg(xb + j1 * 3 + 1));
            pz2 = pk2(__ldg(xb + j0 * 3 + 2), __ldg(xb + j1 * 3 + 2));
        }
        du[0] = du[1] = __float_as_uint(1e10f);

        const u32 rbase = smem_u32(&slots[0][0]);
        if (tid < 128) {                   // init both buffers with tag=2
            vsts64(rbase + tid * 8u, 2ull);
            vsts64(rbase + 1024u + tid * 8u, 2ull);
        }
        // per-lane target CTA base (lanes 0..7 post in parallel)
        const u32 tgt = mapa_u32(rbase, (u32)(lane & 7));

        __syncthreads();
        // one-time cluster rendezvous: all CTAs' slots initialized before any
        // remote key write can land
        asm volatile("barrier.cluster.arrive.aligned;" ::: "memory");
        asm volatile("barrier.cluster.wait.aligned;"   ::: "memory");

        u64 ncx = sneg[0], ncy = sneg[1], ncz = sneg[2];   // centroid 0, neg
        float* ob = new_xyz + (size_t)b * NPOINT * 3;
        const bool emitter = (rank == 0) && (tid == FPS_T - 1);
        const u32 myslot = (u32)((rank * 16 + w) << 3);

        for (int it = 0; it < NPOINT; it++) {
            if (emitter) {   // emit un-negated centroid (sign XOR: exact)
                float lx, t0, ly, t1, lz, t2;
                up2(ncx, lx, t0); up2(ncy, ly, t1); up2(ncz, lz, t2);
                ob[it * 3 + 0] = __uint_as_float(__float_as_uint(lx) ^ 0x80000000u);
                ob[it * 3 + 1] = __uint_as_float(__float_as_uint(ly) ^ 0x80000000u);
                ob[it * 3 + 2] = __uint_as_float(__float_as_uint(lz) ^ 0x80000000u);
                if (((it + 1) & (PUB - 1)) == 0) {
                    asm volatile("st.release.gpu.global.s32 [%0], %1;"
                                 :: "l"(&g_progress[b]), "r"(it + 1) : "memory");
                }
            }
            if (it == NPOINT - 1) break;

            // exact jnp order: d = ((dx*dx+dy*dy)+dz*dz); dist = min(dist, d)
            {
                u64 dx = add2(px2, ncx);
                u64 dy = add2(py2, ncy);
                u64 dz = add2(pz2, ncz);
                u64 dd = add2(add2(mul2(dx, dx), mul2(dy, dy)), mul2(dz, dz));
                float a, bq; up2(dd, a, bq);
                du[0] = min(du[0], __float_as_uint(a));
                du[1] = min(du[1], __float_as_uint(bq));
            }

            // argmax over 2 ('>=' keeps left -> smallest k on ties)
            u32 vb = max(du[0], du[1]);
            int kk = (du[0] >= du[1]) ? 0 : 1;
            u32 idx = (u32)(pbase + tid + kk * FPS_T);

            // warp: max value, then min index among holders of the max
            u32 wmax = __reduce_max_sync(0xffffffffu, vb);
            u32 cand = (vb == wmax) ? idx : 0xffffffffu;
            u32 ci   = __reduce_min_sync(0xffffffffu, cand);

            const u32 boff = (u32)((it & 1) << 10);
            const u32 tag  = (u32)(it & 3);
            // lanes 0..7 each post the (warp-uniform) key to one CTA
            if (lane < 8) {
                u64 key = ((u64)wmax << 32)
                        | (u64)(((8191u - ci) << 2) | tag);
                st_cluster64(tgt + boff + myslot, key);
            }

            // poll all 128 slots (4 per lane) until every tag matches
            const u32 pa = rbase + boff + (u32)(lane << 5);
            u64 k0, k1, k2, k3;
            for (;;) {
                asm volatile("ld.volatile.shared.v2.u64 {%0,%1}, [%2];"
                             : "=l"(k0), "=l"(k1) : "r"(pa));
                asm volatile("ld.volatile.shared.v2.u64 {%0,%1}, [%2];"
                             : "=l"(k2), "=l"(k3) : "r"(pa + 16u));
                bool ok = (((u32)k0 & 3u) == tag) & (((u32)k1 & 3u) == tag)
                        & (((u32)k2 & 3u) == tag) & (((u32)k3 & 3u) == tag);
                if (__all_sync(0xffffffffu, ok)) break;
            }

            // reduce 128 keys: 4-way pair-max, then hi/lo REDUX trick
            u64 m01 = (k0 > k1) ? k0 : k1;
            u64 m23 = (k2 > k3) ? k2 : k3;
            u64 m   = (m01 > m23) ? m01 : m23;
            u32 mhi = __reduce_max_sync(0xffffffffu, (u32)(m >> 32));
            u32 mlo = __reduce_max_sync(0xffffffffu,
                                        ((u32)(m >> 32) == mhi) ? (u32)m : 0u);
            const int f = 8191 - (int)(mlo >> 2);

            ncx = sneg[3 * f + 0];   // broadcast LDS.64
            ncy = sneg[3 * f + 1];
            ncz = sneg[3 * f + 2];
        }
        return;
    }

    // ============================ BALL path ================================
    // block j: batch = j&7, chunk = j>>3 (batch-major interleave so early
    // blocks cover the earliest centroids of every batch).
    {
        const int j     = bid - NFPS - NPREP;
        const int b     = j & 7;
        const int chunk = j >> 3;
        const int m     = chunk * BALLW + w;          // centroid in batch
        const int gw    = b * NPOINT + m;

        float4* sxyz = (float4*)dynsmem;              // 16KB tile
        int (*sel)[NSAMPLE] = (int(*)[NSAMPLE])(dynsmem + 2048);

        // wait until prep done AND our 16 centroids are published
        if (tid == 0) {
            const int need = chunk * BALLW + BALLW;
            int p;
            do {
                asm volatile("ld.acquire.gpu.global.s32 %0, [%1];"
                             : "=r"(p) : "l"(&g_prep_done) : "memory");
                if (p < NPREP) __nanosleep(256);
            } while (p < NPREP);
            do {
                asm volatile("ld.acquire.gpu.global.s32 %0, [%1];"
                             : "=r"(p) : "l"(&g_progress[b]) : "memory");
                if (p < need) __nanosleep(256);
            } while (p < need);
        }
        __syncthreads();

        const float4* pk = g_pk + (size_t)b * NN;
        // L1-bypassing centroid read (line may be cached stale by a neighbor)
        const float* c = new_xyz + (size_t)gw * 3;
        const float sx = __ldcg(c + 0), sy = __ldcg(c + 1), sz = __ldcg(c + 2);
        const float sn = __fadd_rn(__fadd_rn(__fmul_rn(sx, sx), __fmul_rn(sy, sy)),
                                   __fmul_rn(sz, sz));

        int cnt = 0;
        bool done = false;
        const int TILE = 1024;
        for (int t = 0; t < NN / TILE; t++) {
            if (__syncthreads_and(done ? 1 : 0)) break;
            {   // cooperative coalesced tile load: 1024 float4, 2 per thread
                const float4* src = pk + t * TILE;
                sxyz[tid]       = __ldg(src + tid);
                sxyz[tid + 512] = __ldg(src + tid + 512);
            }
            __syncthreads();
            if (!done) {
                for (int base = 0; base < TILE; base += 32) {
                    float4 v = sxyz[base + lane];
                    // sqr = (-2*dot + |src|^2) + |dst|^2
                    float dot = __fadd_rn(__fadd_rn(__fmul_rn(sx, v.x), __fmul_rn(sy, v.y)),
                                          __fmul_rn(sz, v.z));
                    float q = __fadd_rn(__fadd_rn(__fmul_rn(-2.0f, dot), sn), v.w);
                    bool ok = (q <= R2);
                    unsigned msk = __ballot_sync(0xffffffffu, ok);
                    if (ok) {
                        int p = cnt + __popc(msk & ((1u << lane) - 1u));
                        if (p < NSAMPLE) sel[w][p] = t * TILE + base + lane;
                    }
                    cnt += __popc(msk);
                    if (cnt >= NSAMPLE) { done = true; break; }
                }
            }
        }
        __syncwarp();

        // pad with first qualifying index (centroid itself always qualifies)
        int cfull = cnt < NSAMPLE ? cnt : NSAMPLE;
        int first = sel[w][0];
        __syncwarp();
        if (lane >= cfull) sel[w][lane] = first;
        __syncwarp();

        float* op = new_points + (size_t)gw * NSAMPLE * OUTCH;

        // centered xyz: one LDG.128 per lane's own sample
        {
            const int idx = sel[w][lane];
            float4 v = __ldg(pk + idx);
            op[lane * OUTCH + 0] = __fsub_rn(v.x, sx);
            op[lane * OUTCH + 1] = __fsub_rn(v.y, sy);
            op[lane * OUTCH + 2] = __fsub_rn(v.z, sz);
        }

        // features: per sample the warp reads one 256B row coalesced
        const float* pb = points + (size_t)b * NN * DD;
#pragma unroll 4
        for (int s = 0; s < NSAMPLE; s++) {
            int is = sel[w][s];                       // smem broadcast
            float2 v = __ldg((const float2*)(pb + (size_t)is * DD) + lane);
            op[s * OUTCH + 3 + 2 * lane]     = v.x;
            op[s * OUTCH + 3 + 2 * lane + 1] = v.y;
        }
    }
}

// ---------------------------------------------------------------------------
extern "C" void kernel_launch(void* const* d_in, const int* in_sizes, int n_in,
                              void* d_out, int out_size) {
    const float* xyz    = (const float*)d_in[0];
    const float* points = (const float*)d_in[1];

    float* new_xyz    = (float*)d_out;
    float* new_points = (float*)d_out + (size_t)BB * NPOINT * 3;

    cudaFuncSetAttribute(mega_kernel,
                         cudaFuncAttributeMaxDynamicSharedMemorySize, DYN_SMEM);

    init_kernel<<<1, 32>>>();
    mega_kernel<<<NFPS + NPREP + NBALL, FPS_T, DYN_SMEM>>>(xyz, points,
                                                           new_xyz, new_points);
}

// round 14
// speedup vs baseline: 1.1294x; 1.1294x over previous
#include <cuda_runtime.h>
#include <cstdint>

// Problem constants (fixed by setup_inputs)
#define BB 8
#define NN 8192
#define NPOINT 1024
#define NSAMPLE 32
#define DD 64
#define R2 0.0625f
#define OUTCH 67  // 3 + 64

#define FPS_T 512               // threads per block (uniform)
#define CL 4                    // cluster size = FPS CTAs per batch
#define NFPS (BB * CL)          // 32 FPS blocks
#define PTS_CTA (NN / CL)       // 2048 points per FPS CTA
#define NPREP 128               // prep blocks (512 pts each)
#define BALLW 16                // warps (= centroids) per ball block
#define NBALL (BB * NPOINT / BALLW)   // 512 ball blocks
#define DYN_SMEM 196608         // 192KB for every block -> 1 block/SM
#define PUB 16                  // FPS progress publish granularity

using u64 = unsigned long long;
using u32 = unsigned int;

// ---- packed f32x2 helpers (per-lane IEEE RN, bit-identical to scalar RN ops)
__device__ __forceinline__ u64 pk2(float lo, float hi) {
    u64 r; asm("mov.b64 %0, {%1,%2};" : "=l"(r) : "f"(lo), "f"(hi)); return r;
}
__device__ __forceinline__ void up2(u64 v, float& lo, float& hi) {
    asm("mov.b64 {%0,%1}, %2;" : "=f"(lo), "=f"(hi) : "l"(v));
}
__device__ __forceinline__ u64 add2(u64 a, u64 b) {
    u64 r; asm("add.rn.f32x2 %0, %1, %2;" : "=l"(r) : "l"(a), "l"(b)); return r;
}
__device__ __forceinline__ u64 mul2(u64 a, u64 b) {
    u64 r; asm("mul.rn.f32x2 %0, %1, %2;" : "=l"(r) : "l"(a), "l"(b)); return r;
}
__device__ __forceinline__ u32 smem_u32(const void* p) {
    u32 a;
    asm("{ .reg .u64 t; cvta.to.shared.u64 t, %1; cvt.u32.u64 %0, t; }"
        : "=r"(a) : "l"(p));
    return a;
}
__device__ __forceinline__ u32 mapa_u32(u32 a, u32 rank) {
    u32 o; asm("mapa.shared::cluster.u32 %0, %1, %2;" : "=r"(o) : "r"(a), "r"(rank));
    return o;
}
__device__ __forceinline__ u64 vlds64(u32 a) {
    u64 v; asm volatile("ld.volatile.shared.b64 %0, [%1];" : "=l"(v) : "r"(a));
    return v;
}
__device__ __forceinline__ void vsts64(u32 a, u64 v) {
    asm volatile("st.volatile.shared.b64 [%0], %1;" :: "r"(a), "l"(v) : "memory");
}
__device__ __forceinline__ void st_cluster64(u32 a, u64 v) {
    asm volatile("st.shared::cluster.b64 [%0], %1;" :: "r"(a), "l"(v) : "memory");
}

// ---------------------------------------------------------------------------
// Device scratch + producer/consumer counters (zeroed per launch by init)
// ---------------------------------------------------------------------------
__device__ float4 g_pk[BB * NN];   // packed {x,y,z,|p|^2}
__device__ int    g_progress[BB];  // FPS steps published per batch
__device__ int    g_prep_done;     // prep blocks completed

__global__ void init_kernel() {
    if (threadIdx.x < BB) g_progress[threadIdx.x] = 0;
    if (threadIdx.x == BB) g_prep_done = 0;
}

// ---------------------------------------------------------------------------
// Mega kernel, cluster size 4. Blocks 0..31: FPS. 32..159: prep. 160..671:
// ball. FPS clusters are exactly blocks 4c..4c+3, so prep/ball clusters never
// execute cluster ops.
//
// FPS: barrier-free warp-key all-to-all + DESIGNATED POLLER (new vs R12):
//  - per step each warp: packed exact dist update (bit-identical to jnp),
//    u32-domain argmax, warp REDUX pair ->
//    key = (val<<32) | ((8191-idx)<<2) | (it&3). REDUX results are
//    warp-uniform, so lanes 0..3 EACH post the key to one CTA (parallel
//    posting; 8B aligned store = atomic; key IS the payload -> no fence).
//  - ONLY WARP0 polls the 64 slots (2/lane, ld.volatile.v2.u64), reduces
//    (pair-max + hi/lo REDUX), and lane0 publishes the winning key to a
//    local bcast[it&1] slot. Warps 1..15 poll that single slot (broadcast
//    LDS.64, conflict-free) -- 16x less poll traffic than R12/R13; R13's
//    regression was exactly this poll bandwidth (L1 16.9% -> 40.6%).
//  - tags: winning key carries tag it&3 (all step-it keys do). Slot AND
//    bcast reuse safety: buffer b's consecutive users are steps it, it+2
//    with different tags; a writer reaches step it+2 only after consuming
//    step it+1, which transitively requires every warp to have consumed
//    step it. Slots/bcast init to tag=2; one startup cluster.sync. NO
//    per-step barrier or fence of any scope.
//  - max key = max value, ties -> max(8191-idx) = smallest index =
//    jnp.argmax first-occurrence (tag bits equal across a step).
// ---------------------------------------------------------------------------
__global__ void __launch_bounds__(FPS_T, 1) __cluster_dims__(CL, 1, 1)
mega_kernel(const float* __restrict__ xyz, const float* __restrict__ points,
            float* __restrict__ new_xyz, float* __restrict__ new_points) {
    extern __shared__ u64 dynsmem[];
    const int bid = blockIdx.x;
    const int tid = threadIdx.x;
    const int lane = tid & 31;
    const int w    = tid >> 5;

    // =========================== PREP path ================================
    if (bid >= NFPS && bid < NFPS + NPREP) {
        int i = (bid - NFPS) * FPS_T + tid;      // 0 .. BB*NN-1
        const float* p = xyz + (size_t)i * 3;
        float x = __ldg(p + 0), y = __ldg(p + 1), z = __ldg(p + 2);
        float dn = __fadd_rn(__fadd_rn(__fmul_rn(x, x), __fmul_rn(y, y)),
                             __fmul_rn(z, z));
        g_pk[i] = make_float4(x, y, z, dn);
        __syncthreads();
        if (tid == 0) {
            int dummy;
            asm volatile("atom.add.release.gpu.global.s32 %0, [%1], 1;"
                         : "=r"(dummy) : "l"(&g_prep_done) : "memory");
        }
        return;
    }

    // ============================ FPS path =================================
    if (bid < NFPS) {
        u64* sneg = dynsmem;                      // [NN*3] negated dup table
        __shared__ u64 slots[2][64];              // [buf][cta*16+warp]
        __shared__ u64 bcast[2];                  // [buf] winner key

        const int b       = bid >> 2;
        const u32 rank    = bid & 3;
        const int pbase   = rank * PTS_CTA;
        const float* xb   = xyz + (size_t)b * NN * 3;

        // full-batch negated table (every CTA keeps its own copy)
        for (int j = tid; j < NN; j += FPS_T) {
            float x = __ldg(xb + j * 3 + 0);
            float y = __ldg(xb + j * 3 + 1);
            float z = __ldg(xb + j * 3 + 2);
            sneg[3 * j + 0] = pk2(-x, -x);
            sneg[3 * j + 1] = pk2(-y, -y);
            sneg[3 * j + 2] = pk2(-z, -z);
        }
        // own 4 points (k = 0..3 at pbase + tid + k*512), packed by pairs
        u64 px2[2], py2[2], pz2[2];
        u32 du[4];
#pragma unroll
        for (int p = 0; p < 2; p++) {
            int j0 = pbase + tid + (2 * p) * FPS_T;
            int j1 = pbase + tid + (2 * p + 1) * FPS_T;
            px2[p] = pk2(__ldg(xb + j0 * 3 + 0), __ldg(xb + j1 * 3 + 0));
            py2[p] = pk2(__ldg(xb + j0 * 3 + 1), __ldg(xb + j1 * 3 + 1));
            pz2[p] = pk2(__ldg(xb + j0 * 3 + 2), __ldg(xb + j1 * 3 + 2));
        }
#pragma unroll
        for (int k = 0; k < 4; k++) du[k] = __float_as_uint(1e10f);

        const u32 rbase = smem_u32(&slots[0][0]);
        const u32 bbase = smem_u32(&bcast[0]);
        if (tid < 64) {                    // init both buffers with tag=2
            vsts64(rbase + tid * 8u, 2ull);
            vsts64(rbase + 512u + tid * 8u, 2ull);
        }
        if (tid < 2) vsts64(bbase + tid * 8u, 2ull);

        // per-lane target CTA base (lanes 0..3 post in parallel)
        const u32 tgt = mapa_u32(rbase, (u32)(lane & 3));

        __syncthreads();
        // one-time cluster rendezvous: all CTAs' slots initialized before any
        // remote key write can land
        asm volatile("barrier.cluster.arrive.aligned;" ::: "memory");
        asm volatile("barrier.cluster.wait.aligned;"   ::: "memory");

        u64 ncx = sneg[0], ncy = sneg[1], ncz = sneg[2];   // centroid 0, neg
        float* ob = new_xyz + (size_t)b * NPOINT * 3;
        const bool emitter = (rank == 0) && (tid == FPS_T - 1);
        const u32 myslot = (u32)((rank * 16 + w) << 3);

        for (int it = 0; it < NPOINT; it++) {
            if (emitter) {   // emit un-negated centroid (sign XOR: exact)
                float lx, t0, ly, t1, lz, t2;
                up2(ncx, lx, t0); up2(ncy, ly, t1); up2(ncz, lz, t2);
                ob[it * 3 + 0] = __uint_as_float(__float_as_uint(lx) ^ 0x80000000u);
                ob[it * 3 + 1] = __uint_as_float(__float_as_uint(ly) ^ 0x80000000u);
                ob[it * 3 + 2] = __uint_as_float(__float_as_uint(lz) ^ 0x80000000u);
                if (((it + 1) & (PUB - 1)) == 0) {
                    asm volatile("st.release.gpu.global.s32 [%0], %1;"
                                 :: "l"(&g_progress[b]), "r"(it + 1) : "memory");
                }
            }
            if (it == NPOINT - 1) break;

            // exact jnp order: d = ((dx*dx+dy*dy)+dz*dz); dist = min(dist, d)
#pragma unroll
            for (int p = 0; p < 2; p++) {
                u64 dx = add2(px2[p], ncx);
                u64 dy = add2(py2[p], ncy);
                u64 dz = add2(pz2[p], ncz);
                u64 dd = add2(add2(mul2(dx, dx), mul2(dy, dy)), mul2(dz, dz));
                float a, bq; up2(dd, a, bq);
                du[2 * p]     = min(du[2 * p],     __float_as_uint(a));
                du[2 * p + 1] = min(du[2 * p + 1], __float_as_uint(bq));
            }

            // argmax tree over 4 ('>=' keeps left -> smallest k on ties)
            u32 v01 = max(du[0], du[1]); int k01 = (du[0] >= du[1]) ? 0 : 1;
            u32 v23 = max(du[2], du[3]); int k23 = (du[2] >= du[3]) ? 2 : 3;
            u32 vb  = max(v01, v23);     int kk  = (v01 >= v23) ? k01 : k23;
            u32 idx = (u32)(pbase + tid + kk * FPS_T);

            // warp: max value, then min index among holders of the max
            u32 wmax = __reduce_max_sync(0xffffffffu, vb);
            u32 cand = (vb == wmax) ? idx : 0xffffffffu;
            u32 ci   = __reduce_min_sync(0xffffffffu, cand);

            const u32 boff = (u32)((it & 1) << 9);
            const u32 tag  = (u32)(it & 3);
            // lanes 0..3 each post the (warp-uniform) key to one CTA
            u64 key = ((u64)wmax << 32) | (u64)(((8191u - ci) << 2) | tag);
            if (lane < 4) st_cluster64(tgt + boff + myslot, key);

            u64 win;
            if (w == 0) {
                // designated poller: all 64 slots (2 per lane)
                const u32 pa = rbase + boff + (u32)(lane << 4);
                u64 k0, k1;
                for (;;) {
                    asm volatile("ld.volatile.shared.v2.u64 {%0,%1}, [%2];"
                                 : "=l"(k0), "=l"(k1) : "r"(pa));
                    bool ok = (((u32)k0 & 3u) == tag) & (((u32)k1 & 3u) == tag);
                    if (__all_sync(0xffffffffu, ok)) break;
                }
                u64 m = (k0 > k1) ? k0 : k1;
                u32 mhi = __reduce_max_sync(0xffffffffu, (u32)(m >> 32));
                u32 mlo = __reduce_max_sync(0xffffffffu,
                                            ((u32)(m >> 32) == mhi) ? (u32)m : 0u);
                win = ((u64)mhi << 32) | mlo;
                if (lane == 0) vsts64(bbase + ((u32)(it & 1) << 3), win);
            } else {
                // other warps: poll the single broadcast slot
                const u32 ba = bbase + ((u32)(it & 1) << 3);
                for (;;) {
                    win = vlds64(ba);
                    if (((u32)win & 3u) == tag) break;
                }
            }
            const int f = 8191 - (int)(((u32)win) >> 2);

            ncx = sneg[3 * f + 0];   // broadcast LDS.64
            ncy = sneg[3 * f + 1];
            ncz = sneg[3 * f + 2];
        }
        return;
    }

    // ============================ BALL path ================================
    // block j: batch = j&7, chunk = j>>3 (batch-major interleave so early
    // blocks cover the earliest centroids of every batch).
    {
        const int j     = bid - NFPS - NPREP;
        const int b     = j & 7;
        const int chunk = j >> 3;
        const int m     = chunk * BALLW + w;          // centroid in batch
        const int gw    = b * NPOINT + m;

        float4* sxyz = (float4*)dynsmem;              // 16KB tile
        int (*sel)[NSAMPLE] = (int(*)[NSAMPLE])(dynsmem + 2048);

        // wait until prep done AND our 16 centroids are published
        if (tid == 0) {
            const int need = chunk * BALLW + BALLW;
            int p;
            do {
                asm volatile("ld.acquire.gpu.global.s32 %0, [%1];"
                             : "=r"(p) : "l"(&g_prep_done) : "memory");
                if (p < NPREP) __nanosleep(256);
            } while (p < NPREP);
            do {
                asm volatile("ld.acquire.gpu.global.s32 %0, [%1];"
                             : "=r"(p) : "l"(&g_progress[b]) : "memory");
                if (p < need) __nanosleep(256);
            } while (p < need);
        }
        __syncthreads();

        const float4* pk = g_pk + (size_t)b * NN;
        // L1-bypassing centroid read (line may be cached stale by a neighbor)
        const float* c = new_xyz + (size_t)gw * 3;
        const float sx = __ldcg(c + 0), sy = __ldcg(c + 1), sz = __ldcg(c + 2);
        const float sn = __fadd_rn(__fadd_rn(__fmul_rn(sx, sx), __fmul_rn(sy, sy)),
                                   __fmul_rn(sz, sz));

        int cnt = 0;
        bool done = false;
        const int TILE = 1024;
        for (int t = 0; t < NN / TILE; t++) {
            if (__syncthreads_and(done ? 1 : 0)) break;
            {   // cooperative coalesced tile load: 1024 float4, 2 per thread
                const float4* src = pk + t * TILE;
                sxyz[tid]       = __ldg(src + tid);
                sxyz[tid + 512] = __ldg(src + tid + 512);
            }
            __syncthreads();
            if (!done) {
                for (int base = 0; base < TILE; base += 32) {
                    float4 v = sxyz[base + lane];
                    // sqr = (-2*dot + |src|^2) + |dst|^2
                    float dot = __fadd_rn(__fadd_rn(__fmul_rn(sx, v.x), __fmul_rn(sy, v.y)),
                                          __fmul_rn(sz, v.z));
                    float q = __fadd_rn(__fadd_rn(__fmul_rn(-2.0f, dot), sn), v.w);
                    bool ok = (q <= R2);
                    unsigned msk = __ballot_sync(0xffffffffu, ok);
                    if (ok) {
                        int p = cnt + __popc(msk & ((1u << lane) - 1u));
                        if (p < NSAMPLE) sel[w][p] = t * TILE + base + lane;
                    }
                    cnt += __popc(msk);
                    if (cnt >= NSAMPLE) { done = true; break; }
                }
            }
        }
        __syncwarp();

        // pad with first qualifying index (centroid itself always qualifies)
        int cfull = cnt < NSAMPLE ? cnt : NSAMPLE;
        int first = sel[w][0];
        __syncwarp();
        if (lane >= cfull) sel[w][lane] = first;
        __syncwarp();

        float* op = new_points + (size_t)gw * NSAMPLE * OUTCH;

        // centered xyz: one LDG.128 per lane's own sample
        {
            const int idx = sel[w][lane];
            float4 v = __ldg(pk + idx);
            op[lane * OUTCH + 0] = __fsub_rn(v.x, sx);
            op[lane * OUTCH + 1] = __fsub_rn(v.y, sy);
            op[lane * OUTCH + 2] = __fsub_rn(v.z, sz);
        }

        // features: per sample the warp reads one 256B row coalesced
        const float* pb = points + (size_t)b * NN * DD;
#pragma unroll 4
        for (int s = 0; s < NSAMPLE; s++) {
            int is = sel[w][s];                       // smem broadcast
            float2 v = __ldg((const float2*)(pb + (size_t)is * DD) + lane);
            op[s * OUTCH + 3 + 2 * lane]     = v.x;
            op[s * OUTCH + 3 + 2 * lane + 1] = v.y;
        }
    }
}

// ---------------------------------------------------------------------------
extern "C" void kernel_launch(void* const* d_in, const int* in_sizes, int n_in,
                              void* d_out, int out_size) {
    const float* xyz    = (const float*)d_in[0];
    const float* points = (const float*)d_in[1];

    float* new_xyz    = (float*)d_out;
    float* new_points = (float*)d_out + (size_t)BB * NPOINT * 3;

    cudaFuncSetAttribute(mega_kernel,
                         cudaFuncAttributeMaxDynamicSharedMemorySize, DYN_SMEM);

    init_kernel<<<1, 32>>>();
    mega_kernel<<<NFPS + NPREP + NBALL, FPS_T, DYN_SMEM>>>(xyz, points,
                                                           new_xyz, new_points);
}